// round 4
// baseline (speedup 1.0000x reference)
#include <cuda_runtime.h>

#define NN 1024
#define NH 512
#define TC 32          // subband cols per block
#define TR 32          // subband rows per block
#define HALO 70        // 2*32 + 6  (index range 2r+i-3, r<32, i<8 -> [-3,66])
#define TSTRIDE 72     // padded tile row stride

__global__ __launch_bounds__(256, 4)
void wav2d_kernel(const float* __restrict__ x,
                  const float* __restrict__ bmt,
                  float* __restrict__ out)
{
    __shared__ float tile[HALO * TSTRIDE];   // 20160 B
    __shared__ float tmpA[HALO * TC];        //  8960 B (horizontal lo)
    __shared__ float tmpD[HALO * TC];        //  8960 B (horizontal hi)

    const int tid = threadIdx.x;
    const int tx  = tid & 31;   // subband column within tile
    const int ty  = tid >> 5;   // 0..7

    const int b  = blockIdx.z;
    const int r0 = blockIdx.y * TR;
    const int c0 = blockIdx.x * TC;

    // Filters from bmt (L=8):
    //   dec_lo[j] = bmt[7-j]
    //   dec_hi[j] = -(-1)^j * bmt[j]  ->  even j: -bmt[j], odd j: +bmt[j]
    float lo[8], hi[8];
    #pragma unroll
    for (int j = 0; j < 8; ++j) {
        float v = __ldg(&bmt[j]);
        hi[j] = (j & 1) ? v : -v;
        lo[7 - j] = v;
    }

    const float* xb = x + (size_t)b * NN * NN;
    const int gr0 = 2 * r0 - 3;
    const int gc0 = 2 * c0 - 3;

    // ---- Load 70x70 halo tile (periodic wrap; wrap only ever by <= N) ----
    for (int i = tid; i < HALO * HALO; i += 256) {
        int lr = i / HALO;
        int lc = i - lr * HALO;
        int gr = gr0 + lr; if (gr < 0) gr += NN; else if (gr >= NN) gr -= NN;
        int gc = gc0 + lc; if (gc < 0) gc += NN; else if (gc >= NN) gc -= NN;
        tile[lr * TSTRIDE + lc] = __ldg(&xb[gr * NN + gc]);
    }
    __syncthreads();

    // ---- Horizontal pass: 70 rows x 32 cols -> tmpA/tmpD ----
    for (int row = ty; row < HALO; row += 8) {
        const float* trow = &tile[row * TSTRIDE + 2 * tx];
        float sA = 0.f, sD = 0.f;
        #pragma unroll
        for (int j = 0; j < 8; ++j) {
            float v = trow[j];
            sA = fmaf(v, lo[j], sA);
            sD = fmaf(v, hi[j], sD);
        }
        tmpA[row * TC + tx] = sA;
        tmpD[row * TC + tx] = sD;
    }
    __syncthreads();

    // ---- Vertical pass + quadrant stores ----
    // out[R,C]        = vLo(hLo) = cAA
    // out[R,C+512]    = vHi(hLo) = cAD   (top-right)
    // out[R+512,C]    = vLo(hHi) = cDA   (bottom-left)
    // out[R+512,C+512]= vHi(hHi) = cDD
    float* ob = out + (size_t)b * NN * NN;
    #pragma unroll
    for (int k = 0; k < 4; ++k) {
        int rloc = ty + k * 8;                 // 0..31
        float aa = 0.f, ad = 0.f, da = 0.f, dd = 0.f;
        #pragma unroll
        for (int i = 0; i < 8; ++i) {
            float va = tmpA[(2 * rloc + i) * TC + tx];
            float vd = tmpD[(2 * rloc + i) * TC + tx];
            aa = fmaf(va, lo[i], aa);
            ad = fmaf(va, hi[i], ad);
            da = fmaf(vd, lo[i], da);
            dd = fmaf(vd, hi[i], dd);
        }
        int R = r0 + rloc;
        int C = c0 + tx;
        ob[R * NN + C]               = aa;
        ob[R * NN + C + NH]          = ad;
        ob[(R + NH) * NN + C]        = da;
        ob[(R + NH) * NN + C + NH]   = dd;
    }
}

extern "C" void kernel_launch(void* const* d_in, const int* in_sizes, int n_in,
                              void* d_out, int out_size)
{
    const float* x   = (const float*)d_in[0];
    const float* bmt = (const float*)d_in[1];
    float* out = (float*)d_out;

    const int B = in_sizes[0] / (NN * NN);   // 32
    dim3 grid(NH / TC, NH / TR, B);          // (16,16,32) = 8192 CTAs
    wav2d_kernel<<<grid, 256>>>(x, bmt, out);
}

// round 5
// speedup vs baseline: 1.8191x; 1.8191x over previous
#include <cuda_runtime.h>

#define NN 1024
#define NMASK 1023
#define NH 512
#define TC 32          // subband cols per block
#define TR 32          // subband rows per block
#define HROWS 70       // halo rows needed: 2*32 + 6
#define TSTRIDE 72     // tile row stride in floats (= 18 float4, multiple of 4)

__global__ __launch_bounds__(256)
void wav2d_kernel(const float* __restrict__ x,
                  const float* __restrict__ bmt,
                  float* __restrict__ out)
{
    __shared__ float tile[HROWS * TSTRIDE];  // 20160 B, cols = gc0a + [0,72)
    __shared__ float tmpA[HROWS * TC];       //  8960 B
    __shared__ float tmpD[HROWS * TC];       //  8960 B

    const int tid = threadIdx.x;
    const int b  = blockIdx.z;
    const int r0 = blockIdx.y * TR;
    const int c0 = blockIdx.x * TC;

    // Filters (identical to passing round-3 kernel):
    //   dec_lo[j] = bmt[7-j];  dec_hi[j] = (j odd) ? bmt[j] : -bmt[j]
    float lo[8], hi[8];
    #pragma unroll
    for (int j = 0; j < 8; ++j) {
        float v = __ldg(&bmt[j]);
        hi[j] = (j & 1) ? v : -v;
        lo[7 - j] = v;
    }

    const float* xb = x + (size_t)b * NN * NN;
    const int gr0  = 2 * r0 - 3;   // first global row in tile
    const int gc0a = 2 * c0 - 4;   // first global col in tile (16B-aligned when >=0)

    // ---- Load halo tile: 70 rows x 72 cols ----
    const bool interior = (blockIdx.x >= 1) & (blockIdx.x <= 14) &
                          (blockIdx.y >= 1) & (blockIdx.y <= 14);
    if (interior) {
        // fully in-bounds, aligned float4 path: 70*18 = 1260 vectors
        const float4* src = (const float4*)(xb + (size_t)gr0 * NN + gc0a);
        #pragma unroll
        for (int it = 0; it < 5; ++it) {
            int idx = tid + it * 256;
            if (idx < 1260) {
                int row = idx / 18;
                int col = idx - row * 18;
                float4 v = __ldg(&src[row * (NN / 4) + col]);
                *(float4*)&tile[row * TSTRIDE + col * 4] = v;
            }
        }
    } else {
        // edge path: scalar with power-of-two wrap (works for negatives too)
        for (int idx = tid; idx < HROWS * TSTRIDE; idx += 256) {
            int row = idx / TSTRIDE;
            int col = idx - row * TSTRIDE;
            int gr = (gr0 + row) & NMASK;
            int gc = (gc0a + col) & NMASK;
            tile[row * TSTRIDE + col] = __ldg(&xb[gr * NN + gc]);
        }
    }
    __syncthreads();

    // ---- Horizontal pass: thread = (column pair, row strip) ----
    // Output col c needs tile local cols 2c+1 .. 2c+8 (tile is shifted by -1).
    // Thread covers c = 2*tx4 and 2*tx4+1 -> local cols 4*tx4+1 .. 4*tx4+10,
    // read as 3 aligned float4 at 4*tx4 (12 floats, use f[1..10]).
    {
        const int tx4 = tid & 15;       // column pair index
        const int ty4 = tid >> 4;       // 0..15, row strip
        #pragma unroll
        for (int it = 0; it < 5; ++it) {
            int row = ty4 + it * 16;
            if (row < HROWS) {
                const float4* tr = (const float4*)&tile[row * TSTRIDE + 4 * tx4];
                float4 v0 = tr[0], v1 = tr[1], v2 = tr[2];
                float f[12] = { v0.x, v0.y, v0.z, v0.w,
                                v1.x, v1.y, v1.z, v1.w,
                                v2.x, v2.y, v2.z, v2.w };
                float sA0 = 0.f, sD0 = 0.f, sA1 = 0.f, sD1 = 0.f;
                #pragma unroll
                for (int j = 0; j < 8; ++j) {
                    sA0 = fmaf(f[1 + j], lo[j], sA0);
                    sD0 = fmaf(f[1 + j], hi[j], sD0);
                    sA1 = fmaf(f[3 + j], lo[j], sA1);
                    sD1 = fmaf(f[3 + j], hi[j], sD1);
                }
                *(float2*)&tmpA[row * TC + 2 * tx4] = make_float2(sA0, sA1);
                *(float2*)&tmpD[row * TC + 2 * tx4] = make_float2(sD0, sD1);
            }
        }
    }
    __syncthreads();

    // ---- Vertical pass: thread computes 4 consecutive output rows ----
    // rloc = 4*ty + m (m=0..3) needs tmp rows 8*ty .. 8*ty+13 (14 rows shared).
    {
        const int tx = tid & 31;
        const int ty = tid >> 5;        // 0..7
        float aa[4] = {0,0,0,0}, ad[4] = {0,0,0,0};
        float da[4] = {0,0,0,0}, dd[4] = {0,0,0,0};
        #pragma unroll
        for (int i = 0; i < 14; ++i) {
            float va = tmpA[(8 * ty + i) * TC + tx];
            float vd = tmpD[(8 * ty + i) * TC + tx];
            #pragma unroll
            for (int m = 0; m < 4; ++m) {
                int j = i - 2 * m;
                if (j >= 0 && j < 8) {
                    aa[m] = fmaf(va, lo[j], aa[m]);
                    ad[m] = fmaf(va, hi[j], ad[m]);
                    da[m] = fmaf(vd, lo[j], da[m]);
                    dd[m] = fmaf(vd, hi[j], dd[m]);
                }
            }
        }
        float* ob = out + (size_t)b * NN * NN;
        const int C = c0 + tx;
        #pragma unroll
        for (int m = 0; m < 4; ++m) {
            int R = r0 + 4 * ty + m;
            ob[R * NN + C]                  = aa[m];   // cAA (top-left)
            ob[R * NN + C + NH]             = ad[m];   // cAD (top-right)
            ob[(R + NH) * NN + C]           = da[m];   // cDA (bottom-left)
            ob[(R + NH) * NN + C + NH]      = dd[m];   // cDD (bottom-right)
        }
    }
}

extern "C" void kernel_launch(void* const* d_in, const int* in_sizes, int n_in,
                              void* d_out, int out_size)
{
    const float* x   = (const float*)d_in[0];
    const float* bmt = (const float*)d_in[1];
    float* out = (float*)d_out;

    const int B = in_sizes[0] / (NN * NN);   // 32
    dim3 grid(NH / TC, NH / TR, B);          // (16,16,32) = 8192 CTAs
    wav2d_kernel<<<grid, 256>>>(x, bmt, out);
}

// round 6
// speedup vs baseline: 1.9639x; 1.0796x over previous
#include <cuda_runtime.h>

#define NN 1024
#define NMASK 1023
#define NH 512
#define TC 32          // subband cols per block
#define TR 32          // subband rows per block
#define HROWS 70       // halo rows: 2*32 + 6
#define TSTRIDE 72     // tile row stride in floats (18 float4)

// After the horizontal pass, cols [0,32) of each tile row hold the low-pass
// result (tmpA) and cols [32,64) hold the high-pass result (tmpD). This
// aliasing is safe: each tile row is read and then overwritten exclusively by
// one half-warp, and within a warp the row's LDS precede its STS in program
// order.

__global__ __launch_bounds__(256, 6)
void wav2d_kernel(const float* __restrict__ x,
                  const float* __restrict__ bmt,
                  float* __restrict__ out)
{
    __shared__ float tile[HROWS * TSTRIDE];  // 20160 B total smem

    const int tid = threadIdx.x;
    const int b  = blockIdx.z;
    const int r0 = blockIdx.y * TR;
    const int c0 = blockIdx.x * TC;

    // Filters: dec_lo[j] = bmt[7-j]; dec_hi[j] = (j odd) ? bmt[j] : -bmt[j]
    float lo[8], hi[8];
    #pragma unroll
    for (int j = 0; j < 8; ++j) {
        float v = __ldg(&bmt[j]);
        hi[j] = (j & 1) ? v : -v;
        lo[7 - j] = v;
    }

    const float* xb = x + (size_t)b * NN * NN;
    const int gr0  = 2 * r0 - 3;   // first global row in tile
    const int gc0a = 2 * c0 - 4;   // first global col in tile (16B-aligned)

    // ---- Load halo tile: 70 rows x 72 cols ----
    const bool interior = (blockIdx.x >= 1) & (blockIdx.x <= 14) &
                          (blockIdx.y >= 1) & (blockIdx.y <= 14);
    if (interior) {
        const float4* src = (const float4*)(xb + (size_t)gr0 * NN + gc0a);
        #pragma unroll
        for (int it = 0; it < 5; ++it) {
            int idx = tid + it * 256;
            if (idx < 1260) {                    // 70 * 18
                int row = idx / 18;
                int col = idx - row * 18;
                float4 v = __ldg(&src[row * (NN / 4) + col]);
                *(float4*)&tile[row * TSTRIDE + col * 4] = v;
            }
        }
    } else {
        for (int idx = tid; idx < HROWS * TSTRIDE; idx += 256) {
            int row = idx / TSTRIDE;
            int col = idx - row * TSTRIDE;
            int gr = (gr0 + row) & NMASK;
            int gc = (gc0a + col) & NMASK;
            tile[row * TSTRIDE + col] = __ldg(&xb[gr * NN + gc]);
        }
    }
    __syncthreads();

    // ---- Horizontal pass (in-place into tile cols 0..63) ----
    // Output col c needs tile cols 2c+1 .. 2c+8 (tile shifted by -1).
    // Thread covers cols c=2*tx4, 2*tx4+1 via 3 aligned LDS.128 (f[1..10]).
    {
        const int tx4 = tid & 15;       // column-pair index
        const int ty4 = tid >> 4;       // 0..15 row strip
        #pragma unroll
        for (int it = 0; it < 5; ++it) {
            int row = ty4 + it * 16;
            if (row < HROWS) {
                const float4* tr = (const float4*)&tile[row * TSTRIDE + 4 * tx4];
                float4 v0 = tr[0], v1 = tr[1], v2 = tr[2];
                float f[12] = { v0.x, v0.y, v0.z, v0.w,
                                v1.x, v1.y, v1.z, v1.w,
                                v2.x, v2.y, v2.z, v2.w };
                float sA0 = 0.f, sD0 = 0.f, sA1 = 0.f, sD1 = 0.f;
                #pragma unroll
                for (int j = 0; j < 8; ++j) {
                    sA0 = fmaf(f[1 + j], lo[j], sA0);
                    sD0 = fmaf(f[1 + j], hi[j], sD0);
                    sA1 = fmaf(f[3 + j], lo[j], sA1);
                    sD1 = fmaf(f[3 + j], hi[j], sD1);
                }
                // Overwrite this row: cols [0,32) = A, [32,64) = D
                *(float2*)&tile[row * TSTRIDE + 2 * tx4]      = make_float2(sA0, sA1);
                *(float2*)&tile[row * TSTRIDE + 32 + 2 * tx4] = make_float2(sD0, sD1);
            }
        }
    }
    __syncthreads();

    // ---- Vertical pass: warp-uniform (array, quarter); 8 rows/thread ----
    // warp g: arr = g&1 (0 = from A cols, 1 = from D cols), q = g>>1 (0..3).
    // Output rows 8q..8q+7 need tmp rows 16q..16q+21 (22 rows, sliding window).
    {
        const int tx  = tid & 31;
        const int g   = tid >> 5;       // 0..7
        const int arr = g & 1;
        const int q   = g >> 1;

        float sL[8] = {0,0,0,0,0,0,0,0};   // low-pass vertical (cAA or cDA)
        float sH[8] = {0,0,0,0,0,0,0,0};   // high-pass vertical (cAD or cDD)

        const float* col = &tile[(16 * q) * TSTRIDE + 32 * arr + tx];
        #pragma unroll
        for (int i = 0; i < 22; ++i) {
            float v = col[i * TSTRIDE];
            #pragma unroll
            for (int m = 0; m < 8; ++m) {
                int j = i - 2 * m;
                if (j >= 0 && j < 8) {
                    sL[m] = fmaf(v, lo[j], sL[m]);
                    sH[m] = fmaf(v, hi[j], sH[m]);
                }
            }
        }

        // arr=0: rows R (top half).  arr=1: rows R+NH (bottom half).
        // Low-pass vertical -> left cols, high-pass -> right cols (+NH).
        float* ob = out + (size_t)b * NN * NN + (size_t)(arr * NH) * NN;
        const int C = c0 + tx;
        #pragma unroll
        for (int m = 0; m < 8; ++m) {
            int R = r0 + 8 * q + m;
            ob[R * NN + C]      = sL[m];
            ob[R * NN + C + NH] = sH[m];
        }
    }
}

extern "C" void kernel_launch(void* const* d_in, const int* in_sizes, int n_in,
                              void* d_out, int out_size)
{
    const float* x   = (const float*)d_in[0];
    const float* bmt = (const float*)d_in[1];
    float* out = (float*)d_out;

    const int B = in_sizes[0] / (NN * NN);   // 32
    dim3 grid(NH / TC, NH / TR, B);          // (16,16,32) = 8192 CTAs
    wav2d_kernel<<<grid, 256>>>(x, bmt, out);
}

// round 7
// speedup vs baseline: 2.2399x; 1.1405x over previous
#include <cuda_runtime.h>

#define NN 1024
#define NMASK 1023
#define NH 512
#define TC 32          // subband cols per block
#define TR 32          // subband rows per block
#define HROWS 70       // halo rows: 2*32 + 6
#define TSTRIDE 72     // intermediate row stride in floats

// Phase 1 reads x directly from global (L1/L2-cached, overlapping float4s),
// computes the horizontal filter, and writes only the 70x64 intermediate to
// shared memory: cols [0,32) = low-pass (A), cols [32,64) = high-pass (D).
// Phase 2 does the vertical filter from the intermediate.

__global__ __launch_bounds__(256, 6)
void wav2d_kernel(const float* __restrict__ x,
                  const float* __restrict__ bmt,
                  float* __restrict__ out)
{
    __shared__ float tmp[HROWS * TSTRIDE];   // 20160 B

    const int tid = threadIdx.x;
    const int b  = blockIdx.z;
    const int r0 = blockIdx.y * TR;
    const int c0 = blockIdx.x * TC;

    // Filters: dec_lo[j] = bmt[7-j]; dec_hi[j] = (j odd) ? bmt[j] : -bmt[j]
    float lo[8], hi[8];
    #pragma unroll
    for (int j = 0; j < 8; ++j) {
        float v = __ldg(&bmt[j]);
        hi[j] = (j & 1) ? v : -v;
        lo[7 - j] = v;
    }

    const float* xb = x + (size_t)b * NN * NN;
    const int gr0  = 2 * r0 - 3;   // first halo row (may be negative; wrapped)
    const int gc0a = 2 * c0 - 4;   // first halo col, 16B-aligned when in-bounds

    // ---- Phase 1: horizontal filter, global -> registers -> smem ----
    // Task t (of 70*16=1120): row = t>>4 (0..69), pair = t&15 (output cols
    // 2*pair, 2*pair+1). Needs 12 floats starting at gc0a + 4*pair.
    const bool xint = (blockIdx.x >= 1) & (blockIdx.x <= 14);
    #pragma unroll
    for (int it = 0; it < 5; ++it) {
        int task = tid + it * 256;
        if (task < HROWS * 16) {
            int row  = task >> 4;
            int pair = task & 15;
            int gr = (gr0 + row) & NMASK;
            const float* rowp = xb + (size_t)gr * NN;

            float f[12];
            if (xint) {
                const float4* p = (const float4*)(rowp + gc0a) + pair;
                float4 v0 = __ldg(p), v1 = __ldg(p + 1), v2 = __ldg(p + 2);
                f[0]=v0.x; f[1]=v0.y; f[2]=v0.z;  f[3]=v0.w;
                f[4]=v1.x; f[5]=v1.y; f[6]=v1.z;  f[7]=v1.w;
                f[8]=v2.x; f[9]=v2.y; f[10]=v2.z; f[11]=v2.w;
            } else {
                int base = gc0a + 4 * pair;
                #pragma unroll
                for (int j = 0; j < 12; ++j)
                    f[j] = __ldg(&rowp[(base + j) & NMASK]);
            }

            float sA0 = 0.f, sD0 = 0.f, sA1 = 0.f, sD1 = 0.f;
            #pragma unroll
            for (int j = 0; j < 8; ++j) {
                sA0 = fmaf(f[1 + j], lo[j], sA0);
                sD0 = fmaf(f[1 + j], hi[j], sD0);
                sA1 = fmaf(f[3 + j], lo[j], sA1);
                sD1 = fmaf(f[3 + j], hi[j], sD1);
            }
            *(float2*)&tmp[row * TSTRIDE + 2 * pair]      = make_float2(sA0, sA1);
            *(float2*)&tmp[row * TSTRIDE + 32 + 2 * pair] = make_float2(sD0, sD1);
        }
    }
    __syncthreads();

    // ---- Phase 2: vertical filter, warp-uniform; 8 output rows/thread ----
    // warp g: arr = g&1 (A or D source), q = g>>2... (q = g>>1, 0..3).
    // Output rows 8q..8q+7 need tmp rows 16q..16q+21 (sliding window of 22).
    {
        const int tx  = tid & 31;
        const int g   = tid >> 5;
        const int arr = g & 1;
        const int q   = g >> 1;

        float sL[8] = {0,0,0,0,0,0,0,0};
        float sH[8] = {0,0,0,0,0,0,0,0};

        const float* col = &tmp[(16 * q) * TSTRIDE + 32 * arr + tx];
        #pragma unroll
        for (int i = 0; i < 22; ++i) {
            float v = col[i * TSTRIDE];
            #pragma unroll
            for (int m = 0; m < 8; ++m) {
                int j = i - 2 * m;
                if (j >= 0 && j < 8) {
                    sL[m] = fmaf(v, lo[j], sL[m]);
                    sH[m] = fmaf(v, hi[j], sH[m]);
                }
            }
        }

        // arr=0 -> top half rows; arr=1 -> bottom half (+NH).
        // Vertical low-pass -> left cols; high-pass -> right cols (+NH).
        float* ob = out + (size_t)b * NN * NN + (size_t)(arr * NH) * NN;
        const int C = c0 + tx;
        #pragma unroll
        for (int m = 0; m < 8; ++m) {
            int R = r0 + 8 * q + m;
            ob[R * NN + C]      = sL[m];
            ob[R * NN + C + NH] = sH[m];
        }
    }
}

extern "C" void kernel_launch(void* const* d_in, const int* in_sizes, int n_in,
                              void* d_out, int out_size)
{
    const float* x   = (const float*)d_in[0];
    const float* bmt = (const float*)d_in[1];
    float* out = (float*)d_out;

    const int B = in_sizes[0] / (NN * NN);   // 32
    dim3 grid(NH / TC, NH / TR, B);          // (16,16,32) = 8192 CTAs
    wav2d_kernel<<<grid, 256>>>(x, bmt, out);
}

// round 9
// speedup vs baseline: 2.4223x; 1.0815x over previous
#include <cuda_runtime.h>

#define NN 1024
#define NMASK 1023
#define NH 512
#define TC 32          // subband cols per block
#define TR 32          // subband rows per block
#define HROWS 70       // halo rows: 2*32 + 6
#define TSTRIDE 72     // intermediate row stride in floats

// lo[j] = w[7-j] (index reversal, free); hi[j] = (j odd) ? w[j] : -w[j]
// (negation folded into the FFMA operand modifier, free in SASS).
#define FMA_LO(v, j, s) (s) = fmaf((v), w[7 - (j)], (s))
#define FMA_HI(v, j, s) (s) = ((j) & 1) ? fmaf((v), w[(j)], (s)) \
                                        : fmaf((v), -w[(j)], (s))

__global__ __launch_bounds__(256, 6)
void wav2d_kernel(const float* __restrict__ x,
                  const float* __restrict__ bmt,
                  float* __restrict__ out)
{
    __shared__ float tmp[HROWS * TSTRIDE];   // 20160 B

    const int tid = threadIdx.x;
    const int b  = blockIdx.z;
    const int r0 = blockIdx.y * TR;
    const int c0 = blockIdx.x * TC;

    float w[8];
    #pragma unroll
    for (int j = 0; j < 8; ++j) w[j] = __ldg(&bmt[j]);

    const float* xb = x + (size_t)b * NN * NN;
    const int gr0  = 2 * r0 - 3;   // first halo row (wrapped)
    const int gc0a = 2 * c0 - 4;   // first halo col, 16B-aligned when in-bounds

    // ---- Phase 1: horizontal filter, global -> regs -> smem ----
    // Task t (of 70*8=560): row = t>>3, quad q = t&7 -> output cols 4q..4q+3.
    // Needs 16 input floats at local cols 8q .. 8q+15 (use f[1..14]).
    const bool xint = (blockIdx.x >= 1) & (blockIdx.x <= 14);
    #pragma unroll
    for (int it = 0; it < 3; ++it) {
        int task = tid + it * 256;
        if (task < HROWS * 8) {
            int row = task >> 3;
            int q   = task & 7;
            int gr  = (gr0 + row) & NMASK;
            const float* rowp = xb + (size_t)gr * NN;

            float f[16];
            if (xint) {
                const float4* p = (const float4*)(rowp + gc0a) + 2 * q;
                float4 v0 = __ldg(p),     v1 = __ldg(p + 1);
                float4 v2 = __ldg(p + 2), v3 = __ldg(p + 3);
                f[0]=v0.x;  f[1]=v0.y;  f[2]=v0.z;  f[3]=v0.w;
                f[4]=v1.x;  f[5]=v1.y;  f[6]=v1.z;  f[7]=v1.w;
                f[8]=v2.x;  f[9]=v2.y;  f[10]=v2.z; f[11]=v2.w;
                f[12]=v3.x; f[13]=v3.y; f[14]=v3.z; f[15]=v3.w;
            } else {
                int base = gc0a + 8 * q;
                #pragma unroll
                for (int j = 0; j < 16; ++j)
                    f[j] = __ldg(&rowp[(base + j) & NMASK]);
            }

            float a0=0.f, a1=0.f, a2=0.f, a3=0.f;
            float d0=0.f, d1=0.f, d2=0.f, d3=0.f;
            #pragma unroll
            for (int j = 0; j < 8; ++j) {
                FMA_LO(f[1 + j], j, a0);  FMA_HI(f[1 + j], j, d0);
                FMA_LO(f[3 + j], j, a1);  FMA_HI(f[3 + j], j, d1);
                FMA_LO(f[5 + j], j, a2);  FMA_HI(f[5 + j], j, d2);
                FMA_LO(f[7 + j], j, a3);  FMA_HI(f[7 + j], j, d3);
            }
            *(float4*)&tmp[row * TSTRIDE + 4 * q]      = make_float4(a0, a1, a2, a3);
            *(float4*)&tmp[row * TSTRIDE + 32 + 4 * q] = make_float4(d0, d1, d2, d3);
        }
    }
    __syncthreads();

    // ---- Phase 2: vertical filter, warp-uniform; 8 output rows/thread ----
    // warp g: arr = g&1 (A cols [0,32) or D cols [32,64)), q = g>>1 (0..3).
    // Output rows 8q..8q+7 need tmp rows 16q..16q+21 (sliding window of 22).
    {
        const int tx  = tid & 31;
        const int g   = tid >> 5;
        const int arr = g & 1;
        const int q   = g >> 1;

        float sL[8] = {0,0,0,0,0,0,0,0};
        float sH[8] = {0,0,0,0,0,0,0,0};

        const float* col = &tmp[(16 * q) * TSTRIDE + 32 * arr + tx];
        #pragma unroll
        for (int i = 0; i < 22; ++i) {
            float v = col[i * TSTRIDE];
            #pragma unroll
            for (int m = 0; m < 8; ++m) {
                int j = i - 2 * m;
                if (j >= 0 && j < 8) {
                    FMA_LO(v, j, sL[m]);
                    FMA_HI(v, j, sH[m]);
                }
            }
        }

        // arr=0 -> top half rows; arr=1 -> bottom half (+NH).
        // Vertical low-pass -> left cols; high-pass -> right cols (+NH).
        float* ob = out + (size_t)b * NN * NN + (size_t)(arr * NH) * NN;
        const int C = c0 + tx;
        #pragma unroll
        for (int m = 0; m < 8; ++m) {
            int R = r0 + 8 * q + m;
            ob[R * NN + C]      = sL[m];
            ob[R * NN + C + NH] = sH[m];
        }
    }
}

extern "C" void kernel_launch(void* const* d_in, const int* in_sizes, int n_in,
                              void* d_out, int out_size)
{
    const float* x   = (const float*)d_in[0];
    const float* bmt = (const float*)d_in[1];
    float* out = (float*)d_out;

    const int B = in_sizes[0] / (NN * NN);   // 32
    dim3 grid(NH / TC, NH / TR, B);          // (16,16,32) = 8192 CTAs
    wav2d_kernel<<<grid, 256>>>(x, bmt, out);
}